// round 4
// baseline (speedup 1.0000x reference)
#include <cuda_runtime.h>
#include <math.h>

#define BATCH 8
#define SEQ   1024
#define EMB   768
#define HEADS 12
#define HDIM  64
#define M_ROWS (BATCH*SEQ)   // 8192
#define N_COLS (3*EMB)       // 2304
#define PAD 68               // 64 + 4 pad, keeps float4 alignment, breaks bank conflicts

// Scratch (allocation-free rule: device globals)
__device__ float g_Q[BATCH*HEADS*SEQ*HDIM];
__device__ float g_K[BATCH*HEADS*SEQ*HDIM];
__device__ float g_V[BATCH*HEADS*SEQ*HDIM];
__device__ float g_O[BATCH*HEADS*SEQ*HDIM];

// ---------------------------------------------------------------------------
// Kernel 1: qkv = x @ W + b, scattered into Q/K/V laid out [B,H,S,D]
// 128x128 block tile, BK=8, 256 threads, 8x8 register micro-tile
// ---------------------------------------------------------------------------
__global__ __launch_bounds__(256) void qkv_gemm_kernel(
    const float* __restrict__ x, const float* __restrict__ w,
    const float* __restrict__ bias)
{
    __shared__ float As[8][128];
    __shared__ float Bs[8][128];

    const int tid = threadIdx.x;
    const int rowBase = blockIdx.y * 128;
    const int colBase = blockIdx.x * 128;
    const int tm = tid >> 4;       // 0..15
    const int tn = tid & 15;       // 0..15

    float acc[8][8];
    #pragma unroll
    for (int i = 0; i < 8; i++)
        #pragma unroll
        for (int j = 0; j < 8; j++) acc[i][j] = 0.0f;

    const int aRow = tid >> 1;           // 0..127
    const int aK   = (tid & 1) * 4;      // 0 or 4
    const int bK   = tid >> 5;           // 0..7
    const int bN   = (tid & 31) * 4;     // 0..124

    const float* xg = x + (size_t)(rowBase + aRow) * EMB;

    for (int k0 = 0; k0 < EMB; k0 += 8) {
        float4 av = *(const float4*)(xg + k0 + aK);
        float4 bv = *(const float4*)(w + (size_t)(k0 + bK) * N_COLS + colBase + bN);
        As[aK+0][aRow] = av.x; As[aK+1][aRow] = av.y;
        As[aK+2][aRow] = av.z; As[aK+3][aRow] = av.w;
        *(float4*)&Bs[bK][bN] = bv;
        __syncthreads();

        #pragma unroll
        for (int kk = 0; kk < 8; kk++) {
            float4 a0 = *(const float4*)&As[kk][tm*8];
            float4 a1 = *(const float4*)&As[kk][tm*8+4];
            float4 b0 = *(const float4*)&Bs[kk][tn*8];
            float4 b1 = *(const float4*)&Bs[kk][tn*8+4];
            float a[8] = {a0.x,a0.y,a0.z,a0.w,a1.x,a1.y,a1.z,a1.w};
            float b[8] = {b0.x,b0.y,b0.z,b0.w,b1.x,b1.y,b1.z,b1.w};
            #pragma unroll
            for (int i = 0; i < 8; i++)
                #pragma unroll
                for (int j = 0; j < 8; j++)
                    acc[i][j] = fmaf(a[i], b[j], acc[i][j]);
        }
        __syncthreads();
    }

    // Epilogue: add bias and scatter to Q/K/V [B,H,S,D]
    const int nb = colBase + tn * 8;     // multiple of 8; never crosses a 64 or 768 boundary
    const int which = nb / EMB;
    const int rem   = nb % EMB;
    const int h     = rem / HDIM;
    const int d0    = rem % HDIM;
    float* dst = (which == 0) ? g_Q : (which == 1 ? g_K : g_V);

    float4 bias0 = *(const float4*)(bias + nb);
    float4 bias1 = *(const float4*)(bias + nb + 4);

    #pragma unroll
    for (int i = 0; i < 8; i++) {
        int m  = rowBase + tm * 8 + i;
        int bb = m >> 10;
        int ss = m & 1023;
        float* p = dst + ((size_t)((bb * HEADS + h) * SEQ + ss)) * HDIM + d0;
        float4 v0 = make_float4(acc[i][0]+bias0.x, acc[i][1]+bias0.y,
                                acc[i][2]+bias0.z, acc[i][3]+bias0.w);
        float4 v1 = make_float4(acc[i][4]+bias1.x, acc[i][5]+bias1.y,
                                acc[i][6]+bias1.z, acc[i][7]+bias1.w);
        *(float4*)p       = v0;
        *(float4*)(p + 4) = v1;
    }
}

// ---------------------------------------------------------------------------
// Kernel 2: flash-style attention. One CTA per (b, h, 64-row q tile).
// 128 threads: tx = tid&7 (8 col-groups), ty = tid>>3 (16 row-groups of 4).
// ---------------------------------------------------------------------------
__global__ __launch_bounds__(128) void attn_kernel()
{
    extern __shared__ float sm[];
    float* Qs = sm;                 // 64 x PAD
    float* Ks = Qs + 64 * PAD;
    float* Vs = Ks + 64 * PAD;
    float* Ps = Vs + 64 * PAD;

    const int tid = threadIdx.x;
    const int qt = blockIdx.x;      // 0..15
    const int h  = blockIdx.y;
    const int b  = blockIdx.z;
    const int tx = tid & 7;
    const int ty = tid >> 3;

    const float* Qg = g_Q + ((size_t)((b * HEADS + h) * SEQ + qt * 64)) * HDIM;
    const float* Kg = g_K + ((size_t)(b * HEADS + h)) * SEQ * HDIM;
    const float* Vg = g_V + ((size_t)(b * HEADS + h)) * SEQ * HDIM;

    // Load Q tile, fold in 1/sqrt(D) scale
    #pragma unroll
    for (int u = 0; u < 8; u++) {
        int idx = u * 128 + tid;    // float4 index, 0..1023
        int r = idx >> 4, c4 = idx & 15;
        float4 v = *(const float4*)(Qg + r * HDIM + c4 * 4);
        v.x *= 0.125f; v.y *= 0.125f; v.z *= 0.125f; v.w *= 0.125f;
        *(float4*)&Qs[r * PAD + c4 * 4] = v;
    }

    float m_i[4], l_i[4];
    float o[4][8];
    #pragma unroll
    for (int i = 0; i < 4; i++) {
        m_i[i] = -1e30f; l_i[i] = 0.0f;
        #pragma unroll
        for (int j = 0; j < 8; j++) o[i][j] = 0.0f;
    }

    for (int kt = 0; kt < 16; kt++) {
        __syncthreads();    // protect Ks/Vs/Ps from previous iteration readers
        const float* Kgt = Kg + (size_t)kt * 64 * HDIM;
        const float* Vgt = Vg + (size_t)kt * 64 * HDIM;
        #pragma unroll
        for (int u = 0; u < 8; u++) {
            int idx = u * 128 + tid;
            int r = idx >> 4, c4 = idx & 15;
            *(float4*)&Ks[r * PAD + c4 * 4] = *(const float4*)(Kgt + r * HDIM + c4 * 4);
            *(float4*)&Vs[r * PAD + c4 * 4] = *(const float4*)(Vgt + r * HDIM + c4 * 4);
        }
        __syncthreads();

        // S = Qs @ Ks^T  (4x8 per thread)
        float s[4][8];
        #pragma unroll
        for (int i = 0; i < 4; i++)
            #pragma unroll
            for (int j = 0; j < 8; j++) s[i][j] = 0.0f;

        #pragma unroll
        for (int d4 = 0; d4 < 16; d4++) {
            float4 q[4], k[8];
            #pragma unroll
            for (int i = 0; i < 4; i++)
                q[i] = *(const float4*)&Qs[(ty * 4 + i) * PAD + d4 * 4];
            #pragma unroll
            for (int j = 0; j < 8; j++)
                k[j] = *(const float4*)&Ks[(tx * 8 + j) * PAD + d4 * 4];
            #pragma unroll
            for (int i = 0; i < 4; i++)
                #pragma unroll
                for (int j = 0; j < 8; j++) {
                    s[i][j] = fmaf(q[i].x, k[j].x, s[i][j]);
                    s[i][j] = fmaf(q[i].y, k[j].y, s[i][j]);
                    s[i][j] = fmaf(q[i].z, k[j].z, s[i][j]);
                    s[i][j] = fmaf(q[i].w, k[j].w, s[i][j]);
                }
        }

        // Online softmax per row; write P to smem
        #pragma unroll
        for (int i = 0; i < 4; i++) {
            float mx = s[i][0];
            #pragma unroll
            for (int j = 1; j < 8; j++) mx = fmaxf(mx, s[i][j]);
            #pragma unroll
            for (int off = 1; off < 8; off <<= 1)
                mx = fmaxf(mx, __shfl_xor_sync(0xffffffffu, mx, off));
            float mnew = fmaxf(m_i[i], mx);
            float alpha = __expf(m_i[i] - mnew);
            float rowsum = 0.0f;
            #pragma unroll
            for (int j = 0; j < 8; j++) {
                s[i][j] = __expf(s[i][j] - mnew);
                rowsum += s[i][j];
            }
            #pragma unroll
            for (int off = 1; off < 8; off <<= 1)
                rowsum += __shfl_xor_sync(0xffffffffu, rowsum, off);
            l_i[i] = l_i[i] * alpha + rowsum;
            m_i[i] = mnew;
            #pragma unroll
            for (int j = 0; j < 8; j++) o[i][j] *= alpha;
            *(float4*)&Ps[(ty * 4 + i) * PAD + tx * 8]     = make_float4(s[i][0], s[i][1], s[i][2], s[i][3]);
            *(float4*)&Ps[(ty * 4 + i) * PAD + tx * 8 + 4] = make_float4(s[i][4], s[i][5], s[i][6], s[i][7]);
        }
        __syncthreads();

        // O += P @ V  (rows 4ty+i, cols d = 8tx+j)
        #pragma unroll 4
        for (int c = 0; c < 64; c++) {
            float4 va = *(const float4*)&Vs[c * PAD + tx * 8];
            float4 vb = *(const float4*)&Vs[c * PAD + tx * 8 + 4];
            #pragma unroll
            for (int i = 0; i < 4; i++) {
                float p = Ps[(ty * 4 + i) * PAD + c];
                o[i][0] = fmaf(p, va.x, o[i][0]);
                o[i][1] = fmaf(p, va.y, o[i][1]);
                o[i][2] = fmaf(p, va.z, o[i][2]);
                o[i][3] = fmaf(p, va.w, o[i][3]);
                o[i][4] = fmaf(p, vb.x, o[i][4]);
                o[i][5] = fmaf(p, vb.y, o[i][5]);
                o[i][6] = fmaf(p, vb.z, o[i][6]);
                o[i][7] = fmaf(p, vb.w, o[i][7]);
            }
        }
    }

    float* Og = g_O + ((size_t)((b * HEADS + h) * SEQ + qt * 64)) * HDIM;
    #pragma unroll
    for (int i = 0; i < 4; i++) {
        float inv = 1.0f / l_i[i];
        int r = ty * 4 + i;
        float4 r0 = make_float4(o[i][0]*inv, o[i][1]*inv, o[i][2]*inv, o[i][3]*inv);
        float4 r1 = make_float4(o[i][4]*inv, o[i][5]*inv, o[i][6]*inv, o[i][7]*inv);
        *(float4*)(Og + r * HDIM + tx * 8)     = r0;
        *(float4*)(Og + r * HDIM + tx * 8 + 4) = r1;
    }
}

// ---------------------------------------------------------------------------
// Kernel 3: y = LN(x + attn_out) * gamma + beta. One block per row.
// ---------------------------------------------------------------------------
__global__ __launch_bounds__(256) void resid_ln_kernel(
    const float* __restrict__ x, const float* __restrict__ gamma,
    const float* __restrict__ beta, float* __restrict__ out)
{
    const int m  = blockIdx.x;
    const int bb = m >> 10;
    const int ss = m & 1023;
    const int tid = threadIdx.x;

    float y[3];
    float sum = 0.0f, sumsq = 0.0f;
    #pragma unroll
    for (int u = 0; u < 3; u++) {
        int e = tid + u * 256;
        int h = e >> 6, d = e & 63;
        float v = x[(size_t)m * EMB + e] +
                  g_O[((size_t)((bb * HEADS + h) * SEQ + ss)) * HDIM + d];
        y[u] = v;
        sum += v;
        sumsq = fmaf(v, v, sumsq);
    }

    __shared__ float red0[8], red1[8];
    #pragma unroll
    for (int off = 16; off > 0; off >>= 1) {
        sum   += __shfl_xor_sync(0xffffffffu, sum, off);
        sumsq += __shfl_xor_sync(0xffffffffu, sumsq, off);
    }
    int warp = tid >> 5, lane = tid & 31;
    if (lane == 0) { red0[warp] = sum; red1[warp] = sumsq; }
    __syncthreads();
    if (warp == 0) {
        float a = (lane < 8) ? red0[lane] : 0.0f;
        float b = (lane < 8) ? red1[lane] : 0.0f;
        #pragma unroll
        for (int off = 4; off > 0; off >>= 1) {
            a += __shfl_xor_sync(0xffffffffu, a, off);
            b += __shfl_xor_sync(0xffffffffu, b, off);
        }
        if (lane == 0) { red0[0] = a; red1[0] = b; }
    }
    __syncthreads();

    float mean = red0[0] * (1.0f / EMB);
    float var  = red1[0] * (1.0f / EMB) - mean * mean;
    float inv  = rsqrtf(var + 1e-5f);

    #pragma unroll
    for (int u = 0; u < 3; u++) {
        int e = tid + u * 256;
        out[(size_t)m * EMB + e] = (y[u] - mean) * inv * gamma[e] + beta[e];
    }
}

// ---------------------------------------------------------------------------
extern "C" void kernel_launch(void* const* d_in, const int* in_sizes, int n_in,
                              void* d_out, int out_size)
{
    const float* x     = (const float*)d_in[0];
    const float* w     = (const float*)d_in[1];
    const float* bias  = (const float*)d_in[2];
    const float* gamma = (const float*)d_in[3];
    const float* beta  = (const float*)d_in[4];
    float* out = (float*)d_out;

    dim3 g1(N_COLS / 128, M_ROWS / 128);   // (18, 64)
    qkv_gemm_kernel<<<g1, 256>>>(x, w, bias);

    const int smem = 4 * 64 * PAD * sizeof(float);  // 69632 B
    cudaFuncSetAttribute(attn_kernel, cudaFuncAttributeMaxDynamicSharedMemorySize, smem);
    attn_kernel<<<dim3(SEQ / 64, HEADS, BATCH), 128, smem>>>();

    resid_ln_kernel<<<M_ROWS, 256>>>(x, gamma, beta, out);
}

// round 7
// speedup vs baseline: 1.9996x; 1.9996x over previous
#include <cuda_runtime.h>
#include <math.h>

#define BATCH 8
#define SEQ   1024
#define EMB   768
#define HEADS 12
#define HDIM  64
#define M_ROWS (BATCH*SEQ)   // 8192
#define N_COLS (3*EMB)       // 2304

// Scratch (allocation-free rule: device globals)
__device__ float g_Q[BATCH*HEADS*SEQ*HDIM];
__device__ float g_K[BATCH*HEADS*SEQ*HDIM];
__device__ float g_V[BATCH*HEADS*SEQ*HDIM];
__device__ float g_O[BATCH*HEADS*SEQ*HDIM];

// ---------------------------------------------------------------------------
// Kernel 1: qkv = x @ W + b, scattered into Q/K/V laid out [B,H,S,D]
// 128x128 block tile, BK=8, 256 threads, 8x8 micro-tile, double-buffered smem
// ---------------------------------------------------------------------------
__global__ __launch_bounds__(256) void qkv_gemm_kernel(
    const float* __restrict__ x, const float* __restrict__ w,
    const float* __restrict__ bias)
{
    __shared__ float As[2][8][128];
    __shared__ float Bs[2][8][128];

    const int tid = threadIdx.x;
    const int rowBase = blockIdx.y * 128;
    const int colBase = blockIdx.x * 128;
    const int tm = tid >> 4;       // 0..15
    const int tn = tid & 15;       // 0..15

    float acc[8][8];
    #pragma unroll
    for (int i = 0; i < 8; i++)
        #pragma unroll
        for (int j = 0; j < 8; j++) acc[i][j] = 0.0f;

    const int aRow = tid >> 1;           // 0..127
    const int aK   = (tid & 1) * 4;      // 0 or 4
    const int bK   = tid >> 5;           // 0..7
    const int bN   = (tid & 31) * 4;     // 0..124

    const float* xg = x + (size_t)(rowBase + aRow) * EMB;

    // Preload first k-slab
    float4 av = *(const float4*)(xg + aK);
    float4 bv = *(const float4*)(w + (size_t)bK * N_COLS + colBase + bN);
    As[0][aK+0][aRow] = av.x; As[0][aK+1][aRow] = av.y;
    As[0][aK+2][aRow] = av.z; As[0][aK+3][aRow] = av.w;
    *(float4*)&Bs[0][bK][bN] = bv;
    __syncthreads();

    int buf = 0;
    for (int k0 = 0; k0 < EMB; k0 += 8) {
        const bool has_next = (k0 + 8 < EMB);
        if (has_next) {
            av = *(const float4*)(xg + k0 + 8 + aK);
            bv = *(const float4*)(w + (size_t)(k0 + 8 + bK) * N_COLS + colBase + bN);
        }

        #pragma unroll
        for (int kk = 0; kk < 8; kk++) {
            float4 a0 = *(const float4*)&As[buf][kk][tm*8];
            float4 a1 = *(const float4*)&As[buf][kk][tm*8+4];
            float4 b0 = *(const float4*)&Bs[buf][kk][tn*8];
            float4 b1 = *(const float4*)&Bs[buf][kk][tn*8+4];
            float a[8] = {a0.x,a0.y,a0.z,a0.w,a1.x,a1.y,a1.z,a1.w};
            float b[8] = {b0.x,b0.y,b0.z,b0.w,b1.x,b1.y,b1.z,b1.w};
            #pragma unroll
            for (int i = 0; i < 8; i++)
                #pragma unroll
                for (int j = 0; j < 8; j++)
                    acc[i][j] = fmaf(a[i], b[j], acc[i][j]);
        }

        if (has_next) {
            const int nb2 = buf ^ 1;
            As[nb2][aK+0][aRow] = av.x; As[nb2][aK+1][aRow] = av.y;
            As[nb2][aK+2][aRow] = av.z; As[nb2][aK+3][aRow] = av.w;
            *(float4*)&Bs[nb2][bK][bN] = bv;
            __syncthreads();
            buf = nb2;
        }
    }

    // Epilogue: add bias and scatter to Q/K/V [B,H,S,D]
    const int nb = colBase + tn * 8;     // multiple of 8; never crosses 64/768 boundaries
    const int which = nb / EMB;
    const int rem   = nb % EMB;
    const int h     = rem / HDIM;
    const int d0    = rem % HDIM;
    float* dst = (which == 0) ? g_Q : (which == 1 ? g_K : g_V);

    float4 bias0 = *(const float4*)(bias + nb);
    float4 bias1 = *(const float4*)(bias + nb + 4);

    #pragma unroll
    for (int i = 0; i < 8; i++) {
        int m  = rowBase + tm * 8 + i;
        int bb = m >> 10;
        int ss = m & 1023;
        float* p = dst + ((size_t)((bb * HEADS + h) * SEQ + ss)) * HDIM + d0;
        float4 v0 = make_float4(acc[i][0]+bias0.x, acc[i][1]+bias0.y,
                                acc[i][2]+bias0.z, acc[i][3]+bias0.w);
        float4 v1 = make_float4(acc[i][4]+bias1.x, acc[i][5]+bias1.y,
                                acc[i][6]+bias1.z, acc[i][7]+bias1.w);
        *(float4*)p       = v0;
        *(float4*)(p + 4) = v1;
    }
}

// ---------------------------------------------------------------------------
// Kernel 2: flash-style attention, conflict-free smem layouts.
// CTA: 256 threads, Q-tile 128 rows, KV-tile 64.
//   ty = tid>>4 (0..15): 8 q-rows each (blocked)
//   tx = tid&15 (0..15): QK kv-cols strided (col = j*16+tx, j<4)
//                        PV d-cols blocked (d = tx*4 + dd, dd<4)
// P kept TRANSPOSED in smem: Pst[col][row] -> PV reads are broadcast float4.
// Bank analysis: pitch 68 (==4 mod 32): K/V lane-stride 68 -> conflict-free /
// optimal 2-phase. Q & Pst loads broadcast.
// ---------------------------------------------------------------------------
#define QP 68     // pitch for Qs/Ks/Vs rows (64 + 4)
#define PP 132    // pitch for Pst rows (128 + 4)

__global__ __launch_bounds__(256, 2) void attn_kernel()
{
    extern __shared__ float sm[];
    float* Qs  = sm;                    // 128 x QP
    float* Ks  = Qs  + 128 * QP;        // 64 x QP
    float* Vs  = Ks  + 64 * QP;         // 64 x QP
    float* Pst = Vs  + 64 * QP;         // 64 x PP  (transposed P)

    const int tid = threadIdx.x;
    const int qt = blockIdx.x;          // 0..7
    const int h  = blockIdx.y;
    const int b  = blockIdx.z;
    const int tx = tid & 15;
    const int ty = tid >> 4;

    const float* Qg = g_Q + ((size_t)((b * HEADS + h) * SEQ + qt * 128)) * HDIM;
    const float* Kg = g_K + ((size_t)(b * HEADS + h)) * SEQ * HDIM;
    const float* Vg = g_V + ((size_t)(b * HEADS + h)) * SEQ * HDIM;

    // Load Q tile (128x64), fold in 1/sqrt(D)
    #pragma unroll
    for (int u = 0; u < 8; u++) {
        int idx = u * 256 + tid;        // float4 index 0..2047
        int r = idx >> 4, c4 = idx & 15;
        float4 v = *(const float4*)(Qg + r * HDIM + c4 * 4);
        v.x *= 0.125f; v.y *= 0.125f; v.z *= 0.125f; v.w *= 0.125f;
        *(float4*)&Qs[r * QP + c4 * 4] = v;
    }

    float m_i[8], l_i[8];
    float o[8][4];
    #pragma unroll
    for (int i = 0; i < 8; i++) {
        m_i[i] = -1e30f; l_i[i] = 0.0f;
        #pragma unroll
        for (int dd = 0; dd < 4; dd++) o[i][dd] = 0.0f;
    }

    for (int kt = 0; kt < 16; kt++) {
        __syncthreads();    // protect Ks/Vs/Pst from previous iteration readers
        const float* Kgt = Kg + (size_t)kt * 64 * HDIM;
        const float* Vgt = Vg + (size_t)kt * 64 * HDIM;
        #pragma unroll
        for (int u = 0; u < 4; u++) {
            int idx = u * 256 + tid;    // 0..1023
            int r = idx >> 4, c4 = idx & 15;
            *(float4*)&Ks[r * QP + c4 * 4] = *(const float4*)(Kgt + r * HDIM + c4 * 4);
            *(float4*)&Vs[r * QP + c4 * 4] = *(const float4*)(Vgt + r * HDIM + c4 * 4);
        }
        __syncthreads();

        // ---- S = Q @ K^T : s[8 rows][4 strided cols] ----
        float s[8][4];
        #pragma unroll
        for (int i = 0; i < 8; i++)
            #pragma unroll
            for (int j = 0; j < 4; j++) s[i][j] = 0.0f;

        #pragma unroll
        for (int d4 = 0; d4 < 16; d4++) {
            float4 kv[4];
            #pragma unroll
            for (int j = 0; j < 4; j++)
                kv[j] = *(const float4*)&Ks[(j * 16 + tx) * QP + d4 * 4];
            #pragma unroll
            for (int half = 0; half < 2; half++) {
                float4 qv[4];
                #pragma unroll
                for (int i2 = 0; i2 < 4; i2++)
                    qv[i2] = *(const float4*)&Qs[(ty * 8 + half * 4 + i2) * QP + d4 * 4];
                #pragma unroll
                for (int i2 = 0; i2 < 4; i2++)
                    #pragma unroll
                    for (int j = 0; j < 4; j++) {
                        float acc = s[half * 4 + i2][j];
                        acc = fmaf(qv[i2].x, kv[j].x, acc);
                        acc = fmaf(qv[i2].y, kv[j].y, acc);
                        acc = fmaf(qv[i2].z, kv[j].z, acc);
                        acc = fmaf(qv[i2].w, kv[j].w, acc);
                        s[half * 4 + i2][j] = acc;
                    }
            }
        }

        // ---- online softmax (reduce over 16 tx lanes) ----
        #pragma unroll
        for (int i = 0; i < 8; i++) {
            float mx = fmaxf(fmaxf(s[i][0], s[i][1]), fmaxf(s[i][2], s[i][3]));
            #pragma unroll
            for (int off = 1; off < 16; off <<= 1)
                mx = fmaxf(mx, __shfl_xor_sync(0xffffffffu, mx, off));
            float mnew = fmaxf(m_i[i], mx);
            float alpha = __expf(m_i[i] - mnew);
            float rowsum = 0.0f;
            #pragma unroll
            for (int j = 0; j < 4; j++) {
                s[i][j] = __expf(s[i][j] - mnew);
                rowsum += s[i][j];
            }
            #pragma unroll
            for (int off = 1; off < 16; off <<= 1)
                rowsum += __shfl_xor_sync(0xffffffffu, rowsum, off);
            l_i[i] = l_i[i] * alpha + rowsum;
            m_i[i] = mnew;
            #pragma unroll
            for (int dd = 0; dd < 4; dd++) o[i][dd] *= alpha;
        }

        // ---- store P transposed: Pst[col][row] ----
        #pragma unroll
        for (int j = 0; j < 4; j++) {
            int col = j * 16 + tx;
            *(float4*)&Pst[col * PP + ty * 8] =
                make_float4(s[0][j], s[1][j], s[2][j], s[3][j]);
            *(float4*)&Pst[col * PP + ty * 8 + 4] =
                make_float4(s[4][j], s[5][j], s[6][j], s[7][j]);
        }
        __syncthreads();

        // ---- O += P @ V : o[8 rows][4 d-cols], d = tx*4+dd ----
        #pragma unroll 4
        for (int c = 0; c < 64; c++) {
            float4 pa = *(const float4*)&Pst[c * PP + ty * 8];
            float4 pb = *(const float4*)&Pst[c * PP + ty * 8 + 4];
            float4 v  = *(const float4*)&Vs[c * QP + tx * 4];
            o[0][0] = fmaf(pa.x, v.x, o[0][0]); o[0][1] = fmaf(pa.x, v.y, o[0][1]);
            o[0][2] = fmaf(pa.x, v.z, o[0][2]); o[0][3] = fmaf(pa.x, v.w, o[0][3]);
            o[1][0] = fmaf(pa.y, v.x, o[1][0]); o[1][1] = fmaf(pa.y, v.y, o[1][1]);
            o[1][2] = fmaf(pa.y, v.z, o[1][2]); o[1][3] = fmaf(pa.y, v.w, o[1][3]);
            o[2][0] = fmaf(pa.z, v.x, o[2][0]); o[2][1] = fmaf(pa.z, v.y, o[2][1]);
            o[2][2] = fmaf(pa.z, v.z, o[2][2]); o[2][3] = fmaf(pa.z, v.w, o[2][3]);
            o[3][0] = fmaf(pa.w, v.x, o[3][0]); o[3][1] = fmaf(pa.w, v.y, o[3][1]);
            o[3][2] = fmaf(pa.w, v.z, o[3][2]); o[3][3] = fmaf(pa.w, v.w, o[3][3]);
            o[4][0] = fmaf(pb.x, v.x, o[4][0]); o[4][1] = fmaf(pb.x, v.y, o[4][1]);
            o[4][2] = fmaf(pb.x, v.z, o[4][2]); o[4][3] = fmaf(pb.x, v.w, o[4][3]);
            o[5][0] = fmaf(pb.y, v.x, o[5][0]); o[5][1] = fmaf(pb.y, v.y, o[5][1]);
            o[5][2] = fmaf(pb.y, v.z, o[5][2]); o[5][3] = fmaf(pb.y, v.w, o[5][3]);
            o[6][0] = fmaf(pb.z, v.x, o[6][0]); o[6][1] = fmaf(pb.z, v.y, o[6][1]);
            o[6][2] = fmaf(pb.z, v.z, o[6][2]); o[6][3] = fmaf(pb.z, v.w, o[6][3]);
            o[7][0] = fmaf(pb.w, v.x, o[7][0]); o[7][1] = fmaf(pb.w, v.y, o[7][1]);
            o[7][2] = fmaf(pb.w, v.z, o[7][2]); o[7][3] = fmaf(pb.w, v.w, o[7][3]);
        }
    }

    float* Og = g_O + ((size_t)((b * HEADS + h) * SEQ + qt * 128)) * HDIM;
    #pragma unroll
    for (int i = 0; i < 8; i++) {
        float inv = 1.0f / l_i[i];
        *(float4*)(Og + (ty * 8 + i) * HDIM + tx * 4) =
            make_float4(o[i][0]*inv, o[i][1]*inv, o[i][2]*inv, o[i][3]*inv);
    }
}

// ---------------------------------------------------------------------------
// Kernel 3: y = LN(x + attn_out) * gamma + beta. One block per row.
// ---------------------------------------------------------------------------
__global__ __launch_bounds__(256) void resid_ln_kernel(
    const float* __restrict__ x, const float* __restrict__ gamma,
    const float* __restrict__ beta, float* __restrict__ out)
{
    const int m  = blockIdx.x;
    const int bb = m >> 10;
    const int ss = m & 1023;
    const int tid = threadIdx.x;

    float y[3];
    float sum = 0.0f, sumsq = 0.0f;
    #pragma unroll
    for (int u = 0; u < 3; u++) {
        int e = tid + u * 256;
        int h = e >> 6, d = e & 63;
        float v = x[(size_t)m * EMB + e] +
                  g_O[((size_t)((bb * HEADS + h) * SEQ + ss)) * HDIM + d];
        y[u] = v;
        sum += v;
        sumsq = fmaf(v, v, sumsq);
    }

    __shared__ float red0[8], red1[8];
    #pragma unroll
    for (int off = 16; off > 0; off >>= 1) {
        sum   += __shfl_xor_sync(0xffffffffu, sum, off);
        sumsq += __shfl_xor_sync(0xffffffffu, sumsq, off);
    }
    int warp = tid >> 5, lane = tid & 31;
    if (lane == 0) { red0[warp] = sum; red1[warp] = sumsq; }
    __syncthreads();
    if (warp == 0) {
        float a = (lane < 8) ? red0[lane] : 0.0f;
        float bq = (lane < 8) ? red1[lane] : 0.0f;
        #pragma unroll
        for (int off = 4; off > 0; off >>= 1) {
            a  += __shfl_xor_sync(0xffffffffu, a, off);
            bq += __shfl_xor_sync(0xffffffffu, bq, off);
        }
        if (lane == 0) { red0[0] = a; red1[0] = bq; }
    }
    __syncthreads();

    float mean = red0[0] * (1.0f / EMB);
    float var  = red1[0] * (1.0f / EMB) - mean * mean;
    float inv  = rsqrtf(var + 1e-5f);

    #pragma unroll
    for (int u = 0; u < 3; u++) {
        int e = tid + u * 256;
        out[(size_t)m * EMB + e] = (y[u] - mean) * inv * gamma[e] + beta[e];
    }
}

// ---------------------------------------------------------------------------
extern "C" void kernel_launch(void* const* d_in, const int* in_sizes, int n_in,
                              void* d_out, int out_size)
{
    const float* x     = (const float*)d_in[0];
    const float* w     = (const float*)d_in[1];
    const float* bias  = (const float*)d_in[2];
    const float* gamma = (const float*)d_in[3];
    const float* beta  = (const float*)d_in[4];
    float* out = (float*)d_out;

    dim3 g1(N_COLS / 128, M_ROWS / 128);   // (18, 64)
    qkv_gemm_kernel<<<g1, 256>>>(x, w, bias);

    const int smem = (128 * QP + 64 * QP + 64 * QP + 64 * PP) * sizeof(float); // 103424 B
    cudaFuncSetAttribute(attn_kernel, cudaFuncAttributeMaxDynamicSharedMemorySize, smem);
    attn_kernel<<<dim3(SEQ / 128, HEADS, BATCH), 256, smem>>>();

    resid_ln_kernel<<<M_ROWS, 256>>>(x, gamma, beta, out);
}